// round 6
// baseline (speedup 1.0000x reference)
#include <cuda_runtime.h>
#include <cstdint>
#include <math.h>

#define BATCH 16384
#define DIM 64
#define LAMBDA 0.01f
#define TPB 256
#define ROWS 128                        // rows per block
#define GRID (BATCH / ROWS)             // 128 blocks -> single wave
#define ROW_BYTES 256
#define W_OFF 0
#define H_OFF (ROWS * ROW_BYTES)        // 32768
#define U_OFF (2 * ROWS * ROW_BYTES)    // 65536
#define I_OFF (U_OFF + ROWS * 4)
#define S_OFF (I_OFF + ROWS * 4)
#define SMEM_BYTES (S_OFF + ROWS * 4)   // 67072
#define TOTAL_TX (2 * ROWS * ROW_BYTES) // 65536 bytes expected on the mbarrier

__device__ float        g_scratch = 0.0f;
__device__ unsigned int g_count   = 0;

__global__ void __launch_bounds__(TPB) pmf_kernel(
    const int* __restrict__ u,
    const int* __restrict__ iidx,
    const int* __restrict__ s,
    const float* __restrict__ W,
    const float* __restrict__ H,
    float* __restrict__ out)
{
    extern __shared__ char smem[];
    __shared__ __align__(8) uint64_t mbar;

    const int tid  = threadIdx.x;
    const int wid  = tid >> 5;
    const int lane = tid & 31;
    const int base = blockIdx.x * ROWS;

    uint32_t smem_base, mbar_addr;
    asm("{ .reg .u64 t; cvta.to.shared.u64 t, %1; cvt.u32.u64 %0, t; }"
        : "=r"(smem_base) : "l"((void*)smem));
    asm("{ .reg .u64 t; cvta.to.shared.u64 t, %1; cvt.u32.u64 %0, t; }"
        : "=r"(mbar_addr) : "l"((void*)&mbar));

    int* u_s = (int*)(smem + U_OFF);
    int* i_s = (int*)(smem + I_OFF);
    int* s_s = (int*)(smem + S_OFF);

    // stage indices + labels into smem
    if (tid < ROWS) {
        u_s[tid] = __ldg(&u[base + tid]);
        s_s[tid] = __ldg(&s[base + tid]);
    } else {
        const int t = tid - ROWS;
        i_s[t] = __ldg(&iidx[base + t]);
    }
    if (tid == 0) {
        asm volatile("mbarrier.init.shared.b64 [%0], %1;"
                     :: "r"(mbar_addr), "r"(1u) : "memory");
    }
    __syncthreads();

    if (tid == 0) {
        asm volatile("mbarrier.arrive.expect_tx.shared.b64 _, [%0], %1;"
                     :: "r"(mbar_addr), "r"((unsigned)TOTAL_TX) : "memory");
    }

    // 8 warp leaders each issue 16 W-row + 16 H-row bulk copies (async, off the LSU/MSHR path)
    if (lane == 0) {
        const int r0 = wid * 16;
        #pragma unroll
        for (int k = 0; k < 16; k++) {
            const int r = r0 + k;
            const char* wsrc = (const char*)W + (size_t)u_s[r] * ROW_BYTES;
            const char* hsrc = (const char*)H + (size_t)i_s[r] * ROW_BYTES;
            asm volatile(
                "cp.async.bulk.shared::cta.global.mbarrier::complete_tx::bytes [%0], [%1], %2, [%3];"
                :: "r"(smem_base + W_OFF + r * ROW_BYTES), "l"(wsrc),
                   "r"((unsigned)ROW_BYTES), "r"(mbar_addr) : "memory");
            asm volatile(
                "cp.async.bulk.shared::cta.global.mbarrier::complete_tx::bytes [%0], [%1], %2, [%3];"
                :: "r"(smem_base + H_OFF + r * ROW_BYTES), "l"(hsrc),
                   "r"((unsigned)ROW_BYTES), "r"(mbar_addr) : "memory");
        }
    }

    // wait for all 64KB to land (parity 0; kernel instance runs one phase)
    {
        uint32_t done;
        asm volatile(
            "{\n\t.reg .pred p;\n\t"
            "mbarrier.try_wait.parity.acquire.cta.shared::cta.b64 p, [%1], %2;\n\t"
            "selp.b32 %0, 1, 0, p;\n\t}"
            : "=r"(done) : "r"(mbar_addr), "r"(0u) : "memory");
        while (!done) {
            asm volatile(
                "{\n\t.reg .pred p;\n\t"
                "mbarrier.try_wait.parity.acquire.cta.shared::cta.b64 p, [%1], %2, 0x989680;\n\t"
                "selp.b32 %0, 1, 0, p;\n\t}"
                : "=r"(done) : "r"(mbar_addr), "r"(0u) : "memory");
        }
    }

    // compute: 16 groups x 16 lanes, 8 iterations covering 128 rows
    const int grp = tid >> 4;
    const int l16 = tid & 15;
    float acc = 0.0f;

    #pragma unroll
    for (int it = 0; it < 8; it++) {
        const int r = it * 16 + grp;
        const float4 a = ((const float4*)(smem + W_OFF + r * ROW_BYTES))[l16];
        const float4 b = ((const float4*)(smem + H_OFF + r * ROW_BYTES))[l16];

        float dot = a.x * b.x + a.y * b.y + a.z * b.z + a.w * b.w;
        float reg = LAMBDA * (a.x * a.x + a.y * a.y + a.z * a.z + a.w * a.w
                            + b.x * b.x + b.y * b.y + b.z * b.z + b.w * b.w);
        #pragma unroll
        for (int off = 8; off >= 1; off >>= 1) {
            dot += __shfl_down_sync(0xFFFFFFFFu, dot, off);
            reg += __shfl_down_sync(0xFFFFFFFFu, reg, off);
        }
        if (l16 == 0) {
            float x  = dot;
            float ls = fminf(x, 0.0f) - log1pf(expf(-fabsf(x)));  // stable log-sigmoid
            float d  = (float)s_s[r] - ls;
            acc += d * d + reg;
        }
    }

    // block reduction over all 256 threads (acc nonzero only on l16==0 threads)
    #pragma unroll
    for (int off = 16; off >= 1; off >>= 1)
        acc += __shfl_down_sync(0xFFFFFFFFu, acc, off);

    __shared__ float sred[8];
    if (lane == 0) sred[wid] = acc;
    __syncthreads();

    if (tid < 8) {
        float v = sred[tid];
        #pragma unroll
        for (int off = 4; off >= 1; off >>= 1)
            v += __shfl_down_sync(0xFFu, v, off);
        if (tid == 0) {
            asm volatile("red.release.gpu.global.add.f32 [%0], %1;"
                         :: "l"(&g_scratch), "f"(v) : "memory");
            unsigned int old;
            asm volatile("atom.acq_rel.gpu.global.add.u32 %0, [%1], %2;"
                         : "=r"(old) : "l"(&g_count), "r"(1u) : "memory");
            if (old == (unsigned int)(GRID - 1)) {
                unsigned int tot_bits;
                asm volatile("atom.acquire.gpu.global.exch.b32 %0, [%1], %2;"
                             : "=r"(tot_bits) : "l"(&g_scratch), "r"(0u) : "memory");
                g_count = 0;
                out[0] = __int_as_float(tot_bits) * (1.0f / (float)BATCH);
            }
        }
    }
}

extern "C" void kernel_launch(void* const* d_in, const int* in_sizes, int n_in,
                              void* d_out, int out_size) {
    const int*   u = (const int*)d_in[0];
    const int*   i = (const int*)d_in[1];
    const int*   s = (const int*)d_in[2];
    const float* W = (const float*)d_in[3];
    const float* H = (const float*)d_in[4];
    float* out = (float*)d_out;

    static bool attr_set = false;
    if (!attr_set) {
        cudaFuncSetAttribute(pmf_kernel,
                             cudaFuncAttributeMaxDynamicSharedMemorySize, SMEM_BYTES);
        attr_set = true;
    }

    pmf_kernel<<<GRID, TPB, SMEM_BYTES>>>(u, i, s, W, H, out);
}

// round 7
// speedup vs baseline: 1.2330x; 1.2330x over previous
#include <cuda_runtime.h>
#include <math.h>

#define BATCH 16384
#define DIM 64
#define LAMBDA 0.01f
#define TPB 512                          // 16 warps; 32 rows/block (16 lanes per row)
#define GRID (BATCH / 32)                // 512 blocks

__device__ float        g_scratch = 0.0f;
__device__ unsigned int g_count   = 0;

__global__ void __launch_bounds__(TPB) pmf_kernel(
    const int* __restrict__ u,
    const int* __restrict__ iidx,
    const int* __restrict__ s,
    const float4* __restrict__ W4,   // [USER_SIZE * 16]
    const float4* __restrict__ H4,   // [ITEM_SIZE * 16]
    float* __restrict__ out)
{
    const int tid  = threadIdx.x;
    const int grp  = tid >> 4;          // 0..31 row group within block
    const int lane = tid & 15;          // 0..15
    const int row  = blockIdx.x * 32 + grp;

    const int ur = __ldg(&u[row]);
    const int ir = __ldg(&iidx[row]);
    int sv = 0;
    if (lane == 0) sv = __ldg(&s[row]);

    // two independent 16B gathers per thread
    const float4 a = __ldg(&W4[(size_t)ur * 16 + lane]);
    const float4 b = __ldg(&H4[(size_t)ir * 16 + lane]);

    float dot = a.x * b.x + a.y * b.y + a.z * b.z + a.w * b.w;
    float reg = LAMBDA * (a.x * a.x + a.y * a.y + a.z * a.z + a.w * a.w
                        + b.x * b.x + b.y * b.y + b.z * b.z + b.w * b.w);

    #pragma unroll
    for (int off = 8; off >= 1; off >>= 1) {
        dot += __shfl_down_sync(0xFFFFFFFFu, dot, off);
        reg += __shfl_down_sync(0xFFFFFFFFu, reg, off);
    }

    __shared__ float sdata[32];
    if (lane == 0) {
        float x  = dot;
        float ls = fminf(x, 0.0f) - log1pf(expf(-fabsf(x)));   // stable log-sigmoid
        float d  = (float)sv - ls;
        sdata[grp] = d * d + reg;
    }
    __syncthreads();

    // warp 0 folds the 32 per-row contributions and does the block's atomics
    if (tid < 32) {
        float v = sdata[tid];
        #pragma unroll
        for (int off = 16; off >= 1; off >>= 1)
            v += __shfl_down_sync(0xFFFFFFFFu, v, off);
        if (tid == 0) {
            // release add: partial visible before counter bump; no L1-flushing fence
            asm volatile("red.release.gpu.global.add.f32 [%0], %1;"
                         :: "l"(&g_scratch), "f"(v) : "memory");
            unsigned int old;
            asm volatile("atom.acq_rel.gpu.global.add.u32 %0, [%1], %2;"
                         : "=r"(old) : "l"(&g_count), "r"(1u) : "memory");
            if (old == (unsigned int)(GRID - 1)) {
                // last block: fold total into out, reset scratch for next graph replay
                unsigned int tot_bits;
                asm volatile("atom.acquire.gpu.global.exch.b32 %0, [%1], %2;"
                             : "=r"(tot_bits) : "l"(&g_scratch), "r"(0u) : "memory");
                g_count = 0;
                out[0] = __int_as_float(tot_bits) * (1.0f / (float)BATCH);
            }
        }
    }
}

extern "C" void kernel_launch(void* const* d_in, const int* in_sizes, int n_in,
                              void* d_out, int out_size) {
    const int*   u = (const int*)d_in[0];
    const int*   i = (const int*)d_in[1];
    const int*   s = (const int*)d_in[2];
    const float* W = (const float*)d_in[3];
    const float* H = (const float*)d_in[4];
    float* out = (float*)d_out;

    pmf_kernel<<<GRID, TPB>>>(u, i, s,
                              (const float4*)W, (const float4*)H, out);
}

// round 8
// speedup vs baseline: 1.6618x; 1.3478x over previous
#include <cuda_runtime.h>
#include <math.h>

#define BATCH 16384
#define DIM 64
#define LAMBDA 0.01f
#define TPB 256
#define GRID (BATCH / 16)               // 1024 blocks, 16 rows/block
#define CNT_SHIFT 54
#define FIX_SCALE 16777216.0f           // 2^24
#define FIX_INV   (1.0f / 16777216.0f)

// packed accumulator: bits[63:54] = completed-block count, bits[53:0] = fixed-point sum
__device__ unsigned long long g_pack = 0ull;

__global__ void __launch_bounds__(TPB) pmf_kernel(
    const int* __restrict__ u,
    const int* __restrict__ iidx,
    const int* __restrict__ s,
    const float4* __restrict__ W4,   // [USER_SIZE * 16]
    const float4* __restrict__ H4,   // [ITEM_SIZE * 16]
    float* __restrict__ out)
{
    const int tid  = threadIdx.x;
    const int grp  = tid >> 4;          // 0..15
    const int lane = tid & 15;          // 0..15
    const int row  = blockIdx.x * 16 + grp;

    const int ur = __ldg(&u[row]);
    const int ir = __ldg(&iidx[row]);
    int sv = 0;
    if (lane == 0) sv = __ldg(&s[row]);

    // two independent 16B gathers per thread
    const float4 a = __ldg(&W4[(size_t)ur * 16 + lane]);
    const float4 b = __ldg(&H4[(size_t)ir * 16 + lane]);

    float dot = a.x * b.x + a.y * b.y + a.z * b.z + a.w * b.w;
    float reg = LAMBDA * (a.x * a.x + a.y * a.y + a.z * a.z + a.w * a.w
                        + b.x * b.x + b.y * b.y + b.z * b.z + b.w * b.w);

    #pragma unroll
    for (int off = 8; off >= 1; off >>= 1) {
        dot += __shfl_down_sync(0xFFFFFFFFu, dot, off);
        reg += __shfl_down_sync(0xFFFFFFFFu, reg, off);
    }

    __shared__ float sdata[16];
    if (lane == 0) {
        float x  = dot;
        float ls = fminf(x, 0.0f) - log1pf(expf(-fabsf(x)));   // stable log-sigmoid
        float d  = (float)sv - ls;
        sdata[grp] = d * d + reg;                              // strictly positive
    }
    __syncthreads();

    if (tid < 16) {
        float v = sdata[tid];
        #pragma unroll
        for (int off = 8; off >= 1; off >>= 1)
            v += __shfl_down_sync(0xFFFFu, v, off);
        if (tid == 0) {
            // single relaxed 64-bit atomic: payload carries both count and sum,
            // so no fences / release / acquire are needed anywhere.
            const unsigned long long mine =
                (1ull << CNT_SHIFT) | (unsigned long long)__float2ll_rn(v * FIX_SCALE);
            const unsigned long long old = atomicAdd(&g_pack, mine);
            if ((old >> CNT_SHIFT) == (unsigned long long)(GRID - 1)) {
                // we are the last block: old+mine holds the complete packed total
                const unsigned long long total = old + mine;
                const long long fix = (long long)(total & ((1ull << CNT_SHIFT) - 1ull));
                out[0] = (float)fix * FIX_INV * (1.0f / (float)BATCH);
                g_pack = 0ull;   // reset for next graph replay (ordered by launch boundary)
            }
        }
    }
}

extern "C" void kernel_launch(void* const* d_in, const int* in_sizes, int n_in,
                              void* d_out, int out_size) {
    const int*   u = (const int*)d_in[0];
    const int*   i = (const int*)d_in[1];
    const int*   s = (const int*)d_in[2];
    const float* W = (const float*)d_in[3];
    const float* H = (const float*)d_in[4];
    float* out = (float*)d_out;

    pmf_kernel<<<GRID, TPB>>>(u, i, s,
                              (const float4*)W, (const float4*)H, out);
}